// round 6
// baseline (speedup 1.0000x reference)
#include <cuda_runtime.h>
#include <stdint.h>

#define BATCH 16
#define Hdim 1024
#define Wdim 1024
#define NPB (Hdim*Wdim)
#define KTHR 104857
#define TOPK 5
#define CAND_CAP 65536

#define TX 128
#define TY 32
#define HALO 4
#define INW (TX + 2*HALO)
#define INH (TY + 2*HALO)
#define PIN 140
#define PRM 132
#define CBUF 512
#define BANDBUF 2048
#define BLKS_PER_B 256        /* (1024/128)*(1024/32) */

#define PRE_L2 766u            /* (fordu(v)>>22) for v in [1.0,1.5) */
#define FO_GE15 0xBFC00000u    /* fordu(1.5) */

/* ------------ scratch (zero-init at load; re-zeroed every run) ------------ */
__device__ unsigned long long g_cand[BATCH][CAND_CAP];
__device__ unsigned int       g_cand_cnt[BATCH];
__device__ unsigned int       g_cntS[BATCH];
__device__ unsigned int       g_ctrC[BATCH][32];
__device__ float              g_band[BATCH][NPB];
__device__ unsigned int       g_band_cnt[BATCH];
__device__ unsigned int       g_done[BATCH];
__device__ int                g_fb[BATCH];
__device__ unsigned int       g_shift[BATCH];
__device__ unsigned int       g_selpre[BATCH];
__device__ unsigned int       g_rank[BATCH];
__device__ float              g_inbin[BATCH][NPB];
__device__ unsigned int       g_inbin_cnt[BATCH];

__device__ __forceinline__ unsigned int fordu(float f) {
    unsigned int u = __float_as_uint(f);
    return u ^ (unsigned int)(((int)u >> 31) | (int)0x80000000);
}
__device__ __forceinline__ float fordu_inv(unsigned int v) {
    unsigned int u = (v & 0x80000000u) ? (v ^ 0x80000000u) : ~v;
    return __uint_as_float(u);
}
__device__ __forceinline__ unsigned long long umax64(unsigned long long a, unsigned long long b) {
    return a > b ? a : b;
}
#define NEG_INF __int_as_float(0xff800000)
#define BARX(id) asm volatile("bar.sync %0, 256;" :: "r"(id) : "memory")

/* --------- K1: max filter + counting + band collect + candidates +
              (last block per batch) quantile bin select ---------- */
__global__ __launch_bounds__(256) void k1_main(const float* __restrict__ in) {
    __shared__ __align__(16) float s_in[INH * PIN];
    __shared__ __align__(16) float s_rm[INH * PRM];
    __shared__ unsigned long long s_cbuf[CBUF];
    __shared__ float s_band[BANDBUF];
    __shared__ unsigned int s_ccnt, s_cbase, s_cn;
    __shared__ unsigned int s_bcnt, s_bbase, s_bn;
    __shared__ unsigned int s_c32[8][32];
    __shared__ unsigned int s_red[8];
    __shared__ unsigned int s_last;
    __shared__ unsigned int s_selc[32];

    const int b   = blockIdx.z;
    const int tx0 = blockIdx.x * TX;
    const int ty0 = blockIdx.y * TY;
    const float* base = in + (size_t)b * NPB;
    const int tid  = threadIdx.x;
    const int lane = tid & 31;
    const int wid  = tid >> 5;
    const unsigned int lmlt = (1u << lane) - 1u;

    if (tid == 0) { s_ccnt = 0u; s_bcnt = 0u; }
    s_c32[wid][lane] = 0u;

    /* ---------------- load tile + halo ---------------- */
    const bool interior = (blockIdx.x > 0) && (blockIdx.x < (Wdim/TX - 1)) &&
                          (blockIdx.y > 0) && (blockIdx.y < (Hdim/TY - 1));
    if (interior) {
        const float4* gbase = (const float4*)(base + (size_t)(ty0 - HALO) * Wdim + (tx0 - HALO));
        #pragma unroll
        for (int ri = 0; ri < 5; ri++) {
            int r = wid + ri * 8;
            const float4* grow = gbase + (size_t)r * (Wdim / 4);
            float4* srow = (float4*)&s_in[r * PIN];
            srow[lane] = grow[lane];
            if (lane < 2) srow[32 + lane] = grow[32 + lane];
        }
    } else {
        #pragma unroll
        for (int ri = 0; ri < 5; ri++) {
            int r = wid + ri * 8;
            int gy = ty0 + r - HALO;
            bool rowin = (unsigned)gy < (unsigned)Hdim;
            #pragma unroll
            for (int ci = 0; ci < 5; ci++) {
                int c = lane + ci * 32;
                if (c < INW) {
                    int gx = tx0 + c - HALO;
                    float v = NEG_INF;
                    if (rowin && (unsigned)gx < (unsigned)Wdim) v = base[gy * Wdim + gx];
                    s_in[r * PIN + c] = v;
                }
            }
        }
    }
    __syncthreads();

    /* -------- hpass: warp-per-row; counting + band collect fused ---------- */
    unsigned int myS = 0u;
    #pragma unroll
    for (int it = 0; it < 5; it++) {
        int r = wid + it * 8;
        const float4* rf4 = (const float4*)&s_in[r * PIN];
        float4 A = rf4[lane], B = rf4[lane + 1], C = rf4[lane + 2];
        float t[12] = {A.x,A.y,A.z,A.w, B.x,B.y,B.z,B.w, C.x,C.y,C.z,C.w};
        float m2[10], m4[8];
        #pragma unroll
        for (int i = 0; i < 10; i++) m2[i] = fmaxf(t[i], t[i + 1]);
        #pragma unroll
        for (int i = 0; i < 8; i++)  m4[i] = fmaxf(m2[i], m2[i + 2]);
        float4 o;
        o.x = fmaxf(fmaxf(m4[0], m4[4]), t[8]);
        o.y = fmaxf(fmaxf(m4[1], m4[5]), t[9]);
        o.z = fmaxf(fmaxf(m4[2], m4[6]), t[10]);
        o.w = fmaxf(fmaxf(m4[3], m4[7]), t[11]);
        ((float4*)&s_rm[r * PRM])[lane] = o;

        if (r >= HALO && r < HALO + TY) {
            #pragma unroll
            for (int j = 4; j < 8; j++) {
                unsigned int fo = fordu(t[j]);
                if (fo >= FO_GE15) myS++;
                bool inband = ((fo >> 22) == PRE_L2);
                if (inband) atomicAdd(&s_c32[wid][(fo >> 17) & 31u], 1u);
                unsigned int bm = __ballot_sync(0xFFFFFFFFu, inband);
                if (bm) {
                    int ldr = __ffs(bm) - 1;
                    unsigned int bb = 0;
                    if (lane == ldr) bb = atomicAdd(&s_bcnt, (unsigned)__popc(bm));
                    bb = __shfl_sync(0xFFFFFFFFu, bb, ldr);
                    if (inband) {
                        unsigned int p = bb + (unsigned)__popc(bm & lmlt);
                        if (p < BANDBUF) s_band[p] = t[j];
                        else {
                            unsigned int q = atomicAdd(&g_band_cnt[b], 1u);
                            if (q < NPB) g_band[b][q] = t[j];
                        }
                    }
                }
            }
        }
    }
    #pragma unroll
    for (int o = 16; o; o >>= 1) myS += __shfl_xor_sync(0xFFFFFFFFu, myS, o);
    if (lane == 0) s_red[wid] = myS;
    __syncthreads();

    if (tid == 0) {
        unsigned int s = 0;
        #pragma unroll
        for (int w = 0; w < 8; w++) s += s_red[w];
        if (s) atomicAdd(&g_cntS[b], s);
    }
    if (tid < 32) {
        unsigned int s = 0;
        #pragma unroll
        for (int w = 0; w < 8; w++) s += s_c32[w][tid];
        if (s) atomicAdd(&g_ctrC[b][tid], s);
    }

    /* -------- vpass: 9-window vertical max + peak detect ------------------ */
    #pragma unroll
    for (int cc = 0; cc < 2; cc++) {
        int c = tid + cc * 256;
        int x  = c & 127;
        int yc = (c >> 7) << 3;
        float t[16];
        #pragma unroll
        for (int i = 0; i < 16; i++) t[i] = s_rm[(yc + i) * PRM + x];
        float m2[15], m4[13], m8[9];
        #pragma unroll
        for (int i = 0; i < 15; i++) m2[i] = fmaxf(t[i], t[i + 1]);
        #pragma unroll
        for (int i = 0; i < 13; i++) m4[i] = fmaxf(m2[i], m2[i + 2]);
        #pragma unroll
        for (int i = 0; i < 9; i++)  m8[i] = fmaxf(m4[i], m4[i + 4]);
        #pragma unroll
        for (int j = 0; j < 8; j++) {
            float lm = fmaxf(m8[j], t[j + 8]);
            float v  = s_in[(yc + j + HALO) * PIN + x + HALO];
            bool isp = (v == lm);
            unsigned int bm = __ballot_sync(0xFFFFFFFFu, isp);
            if (bm) {
                int ldr = __ffs(bm) - 1;
                unsigned int bb = 0;
                if (lane == ldr) bb = atomicAdd(&s_ccnt, (unsigned)__popc(bm));
                bb = __shfl_sync(0xFFFFFFFFu, bb, ldr);
                if (isp) {
                    unsigned int idx = (unsigned)(ty0 + yc + j) * Wdim + (unsigned)(tx0 + x);
                    unsigned long long key =
                        ((unsigned long long)fordu(v) << 32) | (unsigned long long)(0xFFFFFFFFu - idx);
                    unsigned int p = bb + (unsigned)__popc(bm & lmlt);
                    if (p < CBUF) s_cbuf[p] = key;
                    else {
                        unsigned int q = atomicAdd(&g_cand_cnt[b], 1u);
                        if (q < CAND_CAP) g_cand[b][q] = key;
                    }
                }
            }
        }
    }
    __syncthreads();

    /* -------- flush candidate + band buffers ------------------------------ */
    if (tid == 0) {
        unsigned int n = s_ccnt < CBUF ? s_ccnt : CBUF;
        s_cn = n;
        s_cbase = atomicAdd(&g_cand_cnt[b], n);
        unsigned int m = s_bcnt < BANDBUF ? s_bcnt : BANDBUF;
        s_bn = m;
        s_bbase = atomicAdd(&g_band_cnt[b], m);
    }
    __syncthreads();
    for (unsigned int i = tid; i < s_cn; i += 256) {
        unsigned int q = s_cbase + i;
        if (q < CAND_CAP) g_cand[b][q] = s_cbuf[i];
    }
    for (unsigned int i = tid; i < s_bn; i += 256) {
        unsigned int q = s_bbase + i;
        if (q < NPB) g_band[b][q] = s_band[i];
    }

    /* -------- last block per batch: 32-bin quantile select ---------------- */
    __threadfence();
    __syncthreads();
    if (tid == 0)
        s_last = (atomicAdd(&g_done[b], 1u) == BLKS_PER_B - 1) ? 1u : 0u;
    __syncthreads();
    if (s_last && tid < 32) {
        s_selc[lane] = atomicAdd(&g_ctrC[b][lane], 0u);   /* L2-coherent read */
        unsigned int S = (lane == 0) ? atomicAdd(&g_cntS[b], 0u) : 0u;
        __syncwarp();
        if (lane == 0) {
            atomicExch(&g_done[b], 0u);
            unsigned int cum = S;
            int sel = -1; unsigned int rem = 0;
            for (int j = 31; j >= 0; j--) {
                unsigned int c = s_selc[j];
                if (cum < (unsigned)KTHR && (unsigned)KTHR <= cum + c) {
                    sel = j; rem = (unsigned)KTHR - cum; break;
                }
                cum += c;
            }
            if (sel < 0) g_fb[b] = 1;
            else {
                g_fb[b] = 0;
                g_shift[b]  = 17u;
                g_selpre[b] = (PRE_L2 << 5) | (unsigned)sel;
                g_rank[b]   = rem;
            }
        }
    }
}

/* ---------- KFB: fallback full 12-bit histogram+select (early-exit) ------- */
__global__ __launch_bounds__(1024) void kfb_all(const float* __restrict__ in) {
    const int b = blockIdx.x;
    if (!g_fb[b]) return;
    __shared__ unsigned int s_hist[4096];
    __shared__ unsigned int s_sum[256];
    __shared__ unsigned int s_pref[256];
    const int tid = threadIdx.x;
    for (int i = tid; i < 4096; i += 1024) s_hist[i] = 0u;
    __syncthreads();
    const float4* base = (const float4*)(in + (size_t)b * NPB);
    for (int j = 0; j < 256; j++) {
        float4 v = base[tid + 1024 * j];
        atomicAdd(&s_hist[fordu(v.x) >> 20], 1u);
        atomicAdd(&s_hist[fordu(v.y) >> 20], 1u);
        atomicAdd(&s_hist[fordu(v.z) >> 20], 1u);
        atomicAdd(&s_hist[fordu(v.w) >> 20], 1u);
    }
    __syncthreads();
    if (tid < 256) {
        unsigned int s = 0;
        int hi = 4095 - 16 * tid;
        #pragma unroll
        for (int i = 0; i < 16; i++) s += s_hist[hi - i];
        s_sum[tid] = s;
    }
    __syncthreads();
    if (tid == 0) {
        unsigned int acc = 0;
        for (int j = 0; j < 256; j++) { s_pref[j] = acc; acc += s_sum[j]; }
    }
    __syncthreads();
    if (tid < 256 && s_pref[tid] < (unsigned)KTHR && (unsigned)KTHR <= s_pref[tid] + s_sum[tid]) {
        unsigned int rem = (unsigned)KTHR - s_pref[tid];
        int hi2 = 4095 - 16 * tid;
        for (int i = 0; i < 16; i++) {
            unsigned int c = s_hist[hi2 - i];
            if (rem <= c) {
                g_selpre[b] = (unsigned)(hi2 - i);
                g_shift[b]  = 20u;
                g_rank[b]   = rem;
                break;
            }
            rem -= c;
        }
    }
}

/* ------ K3: compact selected bin from band (or full map on fallback) ------ */
__global__ __launch_bounds__(256) void k3_compact(const float* __restrict__ in) {
    __shared__ float s_buf[4096];
    __shared__ unsigned int s_cnt, s_base, s_n;

    const int b = blockIdx.y;
    const int fb = g_fb[b];
    const unsigned int selpre = g_selpre[b];
    const unsigned int shift  = g_shift[b];
    unsigned int n;
    const float* src;
    if (fb) { n = NPB; src = in + (size_t)b * NPB; }
    else {
        n = g_band_cnt[b];
        if (n > NPB) n = NPB;
        src = g_band[b];
    }
    const int tid = threadIdx.x;
    const float4* s4 = (const float4*)src;

    for (unsigned int start = blockIdx.x * 4096u; start < n; start += 32u * 4096u) {
        if (tid == 0) s_cnt = 0u;
        __syncthreads();
        #pragma unroll
        for (int k = 0; k < 4; k++) {
            unsigned int i4 = start / 4u + tid + 256u * k;
            unsigned int e = i4 * 4u;
            if (e < n) {
                float4 v = s4[i4];
                float a[4] = {v.x, v.y, v.z, v.w};
                #pragma unroll
                for (int j = 0; j < 4; j++) {
                    if (e + j < n && (fordu(a[j]) >> shift) == selpre) {
                        unsigned int p = atomicAdd(&s_cnt, 1u);
                        s_buf[p] = a[j];
                    }
                }
            }
        }
        __syncthreads();
        if (tid == 0) {
            s_n = s_cnt;
            s_base = atomicAdd(&g_inbin_cnt[b], s_cnt);
        }
        __syncthreads();
        for (unsigned int i = tid; i < s_n; i += 256)
            g_inbin[b][s_base + i] = s_buf[i];
        __syncthreads();
    }
}

/* ------ K45: concurrent [threshold refine | top-5 scan] + assembly -------- */
__global__ __launch_bounds__(512) void k45_final(float* __restrict__ out) {
    const int b = blockIdx.x;
    const int tid = threadIdx.x;
    __shared__ unsigned int s_hist[4096];
    __shared__ unsigned int s_sum[256];
    __shared__ unsigned int s_pref[256];
    __shared__ unsigned int s_sel, s_rank2, s_thr;
    __shared__ unsigned long long s_w[8];
    __shared__ unsigned long long s_top[TOPK];
    __shared__ unsigned long long s_amax;

    if (tid < 256) {
        /* =================== phase A: exact threshold ====================== */
        const int tA = tid;
        const unsigned int cnt   = g_inbin_cnt[b] < NPB ? g_inbin_cnt[b] : NPB;
        const unsigned int rank  = g_rank[b];
        const unsigned int shift = g_shift[b];
        const unsigned int lsh   = shift - 12u;
        const unsigned int lmask = (1u << lsh) - 1u;

        for (int i = tA; i < 4096; i += 256) s_hist[i] = 0u;
        BARX(1);
        for (unsigned int bs = 0; bs < cnt; bs += 1024) {
            unsigned int fo[4]; bool ok[4];
            #pragma unroll
            for (int u = 0; u < 4; u++) {
                unsigned int i = bs + tA + 256u * u;
                ok[u] = (i < cnt);
                fo[u] = ok[u] ? fordu(g_inbin[b][i]) : 0u;
            }
            #pragma unroll
            for (int u = 0; u < 4; u++)
                if (ok[u]) atomicAdd(&s_hist[(fo[u] >> lsh) & 0xFFFu], 1u);
        }
        BARX(1);
        {
            unsigned int s = 0;
            int hi = 4095 - 16 * tA;
            #pragma unroll
            for (int i = 0; i < 16; i++) s += s_hist[hi - i];
            s_sum[tA] = s;
        }
        BARX(1);
        if (tA == 0) {
            unsigned int acc = 0;
            for (int j = 0; j < 256; j++) { s_pref[j] = acc; acc += s_sum[j]; }
        }
        BARX(1);
        if (s_pref[tA] < rank && rank <= s_pref[tA] + s_sum[tA]) {
            unsigned int rem = rank - s_pref[tA];
            int hi2 = 4095 - 16 * tA;
            for (int i = 0; i < 16; i++) {
                unsigned int c = s_hist[hi2 - i];
                if (rem <= c) { s_sel = (unsigned)(hi2 - i); s_rank2 = rem; break; }
                rem -= c;
            }
        }
        BARX(1);
        const unsigned int sub = s_sel, rank2 = s_rank2;
        BARX(1);
        if (tA <= (int)lmask) s_hist[tA] = 0u;
        BARX(1);
        for (unsigned int bs = 0; bs < cnt; bs += 1024) {
            unsigned int fo[4]; bool ok[4];
            #pragma unroll
            for (int u = 0; u < 4; u++) {
                unsigned int i = bs + tA + 256u * u;
                ok[u] = (i < cnt);
                fo[u] = ok[u] ? fordu(g_inbin[b][i]) : 0u;
            }
            #pragma unroll
            for (int u = 0; u < 4; u++)
                if (ok[u] && ((fo[u] >> lsh) & 0xFFFu) == sub)
                    atomicAdd(&s_hist[fo[u] & lmask], 1u);
        }
        BARX(1);
        if (tA == 0) {
            unsigned int rem = rank2;
            int bin = (int)lmask;
            for (; bin >= 0; bin--) {
                unsigned int c = s_hist[bin];
                if (rem <= c) break;
                rem -= c;
            }
            s_thr = (g_selpre[b] << shift) | (sub << lsh) | (unsigned int)bin;
        }
    } else {
        /* ============== phase B: unfiltered top-5 + argmax ================= */
        const int tB = tid - 256;
        const int wB = tB >> 5;
        const int laneB = tB & 31;
        unsigned int ccnt = g_cand_cnt[b];
        if (ccnt > CAND_CAP) ccnt = CAND_CAP;

        unsigned long long loc[TOPK];
        unsigned long long amax = 0ull;
        #pragma unroll
        for (int j = 0; j < TOPK; j++) loc[j] = 0ull;

        for (unsigned int bs = 0; bs < ccnt; bs += 2048) {
            unsigned long long kk[8];
            #pragma unroll
            for (int u = 0; u < 8; u++) {
                unsigned int i = bs + tB + 256u * u;
                kk[u] = (i < ccnt) ? g_cand[b][i] : 0ull;
            }
            #pragma unroll
            for (int u = 0; u < 8; u++) {
                amax = umax64(amax, kk[u]);
                if (kk[u] > loc[TOPK - 1]) {
                    loc[TOPK - 1] = kk[u];
                    #pragma unroll
                    for (int j = TOPK - 1; j > 0; j--) {
                        if (loc[j] > loc[j - 1]) {
                            unsigned long long t = loc[j - 1]; loc[j - 1] = loc[j]; loc[j] = t;
                        }
                    }
                }
            }
        }

        int ptr = 0;
        for (int r = 0; r < TOPK; r++) {
            unsigned long long cnd = (ptr < TOPK) ? loc[ptr] : 0ull;
            #pragma unroll
            for (int o = 16; o; o >>= 1)
                cnd = umax64(cnd, __shfl_xor_sync(0xFFFFFFFFu, cnd, o));
            if (laneB == 0) s_w[wB] = cnd;
            BARX(2);
            if (wB == 0) {
                unsigned long long m = (laneB < 8) ? s_w[laneB] : 0ull;
                #pragma unroll
                for (int o = 4; o; o >>= 1)
                    m = umax64(m, __shfl_xor_sync(0xFFFFFFFFu, m, o));
                if (laneB == 0) s_top[r] = m;
            }
            BARX(2);
            unsigned long long w = s_top[r];
            if (ptr < TOPK && loc[ptr] == w && w != 0ull) ptr++;
        }

        #pragma unroll
        for (int o = 16; o; o >>= 1)
            amax = umax64(amax, __shfl_xor_sync(0xFFFFFFFFu, amax, o));
        if (laneB == 0) s_w[wB] = amax;
        BARX(2);
        if (wB == 0) {
            unsigned long long m = (laneB < 8) ? s_w[laneB] : 0ull;
            #pragma unroll
            for (int o = 4; o; o >>= 1)
                m = umax64(m, __shfl_xor_sync(0xFFFFFFFFu, m, o));
            if (laneB == 0) s_amax = m;
        }
        BARX(2);
    }
    __syncthreads();

    /* ---------------------- final assembly (tid 0) ------------------------ */
    if (tid == 0) {
        const unsigned int thr_ord = s_thr;
        float topv[TOPK], xs[TOPK], ys[TOPK];
        bool hp[TOPK];
        #pragma unroll
        for (int j = 0; j < TOPK; j++) {
            unsigned long long k = s_top[j];
            hp[j] = (k != 0ull) && ((unsigned int)(k >> 32) > thr_ord);
            topv[j] = hp[j] ? fordu_inv((unsigned int)(k >> 32)) : NEG_INF;
            unsigned int idx = 0xFFFFFFFFu - (unsigned int)(k & 0xFFFFFFFFull);
            xs[j] = (float)(idx % Wdim);
            ys[j] = (float)(idx / Wdim);
        }
        bool has_any = hp[0];
        if (!has_any) {
            unsigned int fidx = 0xFFFFFFFFu - (unsigned int)(s_amax & 0xFFFFFFFFull);
            xs[0] = (float)(fidx % Wdim);
            ys[0] = (float)(fidx / Wdim);
        }
        float peak_max = topv[0];
        int n_valid = 0;
        #pragma unroll
        for (int j = 0; j < TOPK; j++)
            if (topv[j] >= peak_max * 0.5f && hp[j]) n_valid++;
        if (n_valid < 1) n_valid = 1;
        #pragma unroll
        for (int j = 0; j < TOPK; j++) {
            bool keep = (j < n_valid);
            out[b * (TOPK * 2) + 2 * j + 0] = keep ? xs[j] : -1.0f;
            out[b * (TOPK * 2) + 2 * j + 1] = keep ? ys[j] : -1.0f;
            out[BATCH * TOPK * 2 + b * TOPK + j] = keep ? 1.0f : -1.0f;
        }
    }

    /* ------------- re-zero this batch's state for next replay ------------- */
    __syncthreads();
    if (tid == 0) {
        g_cand_cnt[b]  = 0u;
        g_band_cnt[b]  = 0u;
        g_cntS[b]      = 0u;
        g_inbin_cnt[b] = 0u;
    }
    if (tid < 32) g_ctrC[b][tid] = 0u;
}

/* -------------------------------- launch ---------------------------------- */
extern "C" void kernel_launch(void* const* d_in, const int* in_sizes, int n_in,
                              void* d_out, int out_size) {
    const float* in = (const float*)d_in[0];
    float* out = (float*)d_out;
    (void)in_sizes; (void)n_in; (void)out_size;

    k1_main<<<dim3(Wdim / TX, Hdim / TY, BATCH), 256>>>(in);
    kfb_all<<<BATCH, 1024>>>(in);
    k3_compact<<<dim3(32, BATCH), 256>>>(in);
    k45_final<<<BATCH, 512>>>(out);
}